// round 7
// baseline (speedup 1.0000x reference)
#include <cuda_runtime.h>
#include <math.h>
#include <stdint.h>

#define D_TOT 320
#define DZ    64
#define DX    256
#define DK    256
#define HID   16
#define BATCH 1024
#define NEG   0.01f
#define HALF_LOG2PI 0.91893853320467274f
#define STAGES 8
#define NB_PH0 256      // phase-0 producer blocks (must be <= first-wave capacity)
#define NB_ALL 512      // total blocks (8 x 64)

// scratch (device globals — no allocation allowed)
__device__ float g_E[D_TOT * D_TOT];                 // exp(-mask_param), [j][k]
__device__ ulonglong2 g_W0t[D_TOT * 4 * DK];         // W0 transposed [j][h4][k'], diag zeroed
__device__ float g_accum;
__device__ unsigned int g_done;
__device__ unsigned int g_sync;

__device__ __forceinline__ float lrelu(float v) { return fmaxf(v, NEG * v); }

__device__ __forceinline__ unsigned long long pack2(float lo, float hi) {
    unsigned long long r;
    asm("mov.b64 %0, {%1, %2};" : "=l"(r) : "f"(lo), "f"(hi));
    return r;
}
__device__ __forceinline__ void unpack2(unsigned long long v, float& lo, float& hi) {
    asm("mov.b64 {%0, %1}, %2;" : "=f"(lo), "=f"(hi) : "l"(v));
}
__device__ __forceinline__ void ffma2(unsigned long long& d, unsigned long long a,
                                      unsigned long long b) {
    asm("fma.rn.f32x2 %0, %1, %2, %0;" : "+l"(d) : "l"(a), "l"(b));
}
__device__ __forceinline__ void cp_async16(uint32_t dst, const void* src) {
    asm volatile("cp.async.cg.shared.global [%0], [%1], 16;" :: "r"(dst), "l"(src));
}

// ---------------------------------------------------------------------------
// ONE fused kernel, grid (8,64) = 512 blocks x 256 threads, 2 b per thread.
// Blocks 0..255 run phase 0 (init + latent) and raise g_sync; all blocks wait
// on the flag (producers are all first-wave-resident => no deadlock).
// ---------------------------------------------------------------------------
__global__ void __launch_bounds__(256, 3)
fused_kernel(const float* __restrict__ x,
             const float* __restrict__ z,
             const float* __restrict__ u,
             const float* __restrict__ mp,
             const float* __restrict__ W0,
             const float* __restrict__ b0,
             const float* __restrict__ W1,
             const float* __restrict__ b1,
             const float* __restrict__ W2,
             const float* __restrict__ b2,
             const float* __restrict__ logvar,
             float* __restrict__ out) {
    extern __shared__ float dynsm[];
    float* ss = dynsm;                       // 16*320 floats (all_var, 16 b)
    float* us = dynsm + 16 * D_TOT;          // STAGES*16*32 floats (u tiles)

    int tid  = threadIdx.x;
    int lane = tid & 31;
    int warp = tid >> 5;
    int bid  = blockIdx.x + blockIdx.y * gridDim.x;   // 0..511

    // ---------------- Phase 0 (blocks 0..255 only) ----------------
    if (bid < NB_PH0) {
        int gtid = bid * 256 + tid;                    // 0..65535

        for (int i = gtid; i < D_TOT * 4 * DK; i += NB_PH0 * 256) {
            int kp = i & (DK - 1);
            int h4 = (i >> 8) & 3;
            int j  = i >> 10;
            int k  = DZ + kp;
            float4 v;
            if (j == k) v = make_float4(0.f, 0.f, 0.f, 0.f);
            else        v = *(const float4*)(W0 + ((size_t)k * D_TOT + j) * HID + h4 * 4);
            ulonglong2 p;
            p.x = pack2(v.x, v.y);
            p.y = pack2(v.z, v.w);
            g_W0t[i] = p;
        }
        for (int i = gtid; i < D_TOT * D_TOT; i += NB_PH0 * 256)
            g_E[i] = expf(-mp[i]);
        if (gtid < D_TOT) out[1 + BATCH * D_TOT + gtid] = expf(0.5f * logvar[gtid]);

        // latent item (b = gtid>>6, k = gtid&63)
        {
            int k = gtid & (DZ - 1);
            int b = gtid >> 6;
            float uu = u[((size_t)b * D_TOT + k) * D_TOT + k];
            float E  = expf(-mp[k * D_TOT + k]);
            float s  = z[b * DZ + k];
            float m = __fdividef(uu * s, fmaf(1.0f - uu, E, uu));

            float h1v[HID];
#pragma unroll
            for (int g = 0; g < HID; g++) h1v[g] = b1[k * HID + g];
#pragma unroll
            for (int h = 0; h < HID; h++) {
                float a = lrelu(fmaf(m, W0[((size_t)k * D_TOT + k) * HID + h], b0[k * HID + h]));
                const float* w1r = W1 + (k * HID + h) * HID;
#pragma unroll
                for (int g = 0; g < HID; g++) h1v[g] = fmaf(a, w1r[g], h1v[g]);
            }
            float mu = b2[k];
#pragma unroll
            for (int h = 0; h < HID; h++) mu = fmaf(lrelu(h1v[h]), W2[k * HID + h], mu);

            out[1 + (size_t)b * D_TOT + k] = mu;

            float logstd = 0.5f * logvar[k];
            float istd = __expf(-logstd);
            float diff = (s - mu) * istd;
            float lp = fmaf(-0.5f * diff, diff, -logstd - HALF_LOG2PI);
#pragma unroll
            for (int o = 16; o > 0; o >>= 1) lp += __shfl_down_sync(0xffffffffu, lp, o);
            if (lane == 0) atomicAdd(&g_accum, lp);
        }
        __syncthreads();
        if (tid == 0) { __threadfence(); atomicAdd(&g_sync, 1u); }
    }

    // stage all_var for this block's 16 b's (independent of phase 0)
    for (int idx = tid; idx < 16 * D_TOT; idx += 256) {
        int bl = idx / D_TOT;
        int j  = idx - bl * D_TOT;
        int b  = blockIdx.y * 16 + bl;
        ss[idx] = (j < DZ) ? z[b * DZ + j] : x[b * DX + (j - DZ)];
    }

    // wait for phase 0 completion
    if (tid == 0) {
        while (atomicAdd(&g_sync, 0u) < NB_PH0) { }
        __threadfence();
    }
    __syncthreads();

    // ---------------- Dense: 2 b per thread ----------------
    int kp = blockIdx.x * 32 + lane;            // k' in [0,256)
    int k  = DZ + kp;
    int bbase = blockIdx.y * 16 + warp * 2;     // 2 consecutive b's per thread

    unsigned long long acc[2][8];
#pragma unroll
    for (int h2 = 0; h2 < 8; h2++) {
        unsigned long long p = pack2(b0[k * HID + 2 * h2], b0[k * HID + 2 * h2 + 1]);
        acc[0][h2] = p;
        acc[1][h2] = p;
    }

    const float* srow = &ss[(warp * 2) * D_TOT];
    const ulonglong2* Wt = g_W0t + kp;          // + (j*4 + h4)*DK

    // cp.async: lanes 0..15 fetch; lb = b (0/1), lc = 16B chunk of the 32-k row
    int lb = (lane >> 3) & 1;
    int lc = lane & 7;
    bool fetcher = lane < 16;
    const float* usrc = u + ((size_t)(bbase + lb) * D_TOT) * D_TOT
                          + (DZ + blockIdx.x * 32) + lc * 4;

    uint32_t us_base = (uint32_t)__cvta_generic_to_shared(us);
    // stage slot: stage*2048B + ((warp*2 + lb)*32 + lc*4)*4B
    uint32_t wbase = us_base + (((warp * 2 + lb) * 32 + lc * 4) << 2);
    const float* ur0 = us + (warp * 2) * 32 + lane;

#pragma unroll
    for (int s = 0; s < STAGES - 1; s++) {
        if (fetcher) cp_async16(wbase + (s << 11), usrc + (size_t)s * D_TOT);
        asm volatile("cp.async.commit_group;");
    }

#pragma unroll 2
    for (int j = 0; j < D_TOT; j++) {
        int stage = j & (STAGES - 1);
        asm volatile("cp.async.wait_group %0;" :: "n"(STAGES - 2));
        __syncwarp();

        float E = g_E[j * D_TOT + k];
        ulonglong2 w01 = Wt[(j * 4 + 0) * DK];
        ulonglong2 w23 = Wt[(j * 4 + 1) * DK];
        ulonglong2 w45 = Wt[(j * 4 + 2) * DK];
        ulonglong2 w67 = Wt[(j * 4 + 3) * DK];

        const float* ur = ur0 + (stage << 9);
        float u0 = ur[0];
        float u1 = ur[32];

        {
            float sj = srow[j];
            float m = __fdividef(u0 * sj, fmaf(1.0f - u0, E, u0));
            unsigned long long mm = pack2(m, m);
            ffma2(acc[0][0], mm, w01.x); ffma2(acc[0][1], mm, w01.y);
            ffma2(acc[0][2], mm, w23.x); ffma2(acc[0][3], mm, w23.y);
            ffma2(acc[0][4], mm, w45.x); ffma2(acc[0][5], mm, w45.y);
            ffma2(acc[0][6], mm, w67.x); ffma2(acc[0][7], mm, w67.y);
        }
        {
            float sj = srow[D_TOT + j];
            float m = __fdividef(u1 * sj, fmaf(1.0f - u1, E, u1));
            unsigned long long mm = pack2(m, m);
            ffma2(acc[1][0], mm, w01.x); ffma2(acc[1][1], mm, w01.y);
            ffma2(acc[1][2], mm, w23.x); ffma2(acc[1][3], mm, w23.y);
            ffma2(acc[1][4], mm, w45.x); ffma2(acc[1][5], mm, w45.y);
            ffma2(acc[1][6], mm, w67.x); ffma2(acc[1][7], mm, w67.y);
        }

        int jn = j + STAGES - 1;
        if (jn < D_TOT && fetcher)
            cp_async16(wbase + ((jn & (STAGES - 1)) << 11), usrc + (size_t)jn * D_TOT);
        asm volatile("cp.async.commit_group;");
    }

    // epilogue: layers 1 & 2, mu, logp
    float logstd = 0.5f * logvar[k];
    float istd = __expf(-logstd);
    float lpsum = 0.0f;

#pragma unroll
    for (int i = 0; i < 2; i++) {
        float a0[HID];
#pragma unroll
        for (int h2 = 0; h2 < 8; h2++) unpack2(acc[i][h2], a0[2 * h2], a0[2 * h2 + 1]);

        float h1v[HID];
#pragma unroll
        for (int g = 0; g < HID; g++) h1v[g] = b1[k * HID + g];
#pragma unroll
        for (int h = 0; h < HID; h++) {
            float a = lrelu(a0[h]);
            const float4* w1p = (const float4*)(W1 + ((size_t)k * HID + h) * HID);
            float4 r0 = w1p[0], r1 = w1p[1], r2 = w1p[2], r3 = w1p[3];
            float wr[HID] = {r0.x, r0.y, r0.z, r0.w, r1.x, r1.y, r1.z, r1.w,
                             r2.x, r2.y, r2.z, r2.w, r3.x, r3.y, r3.z, r3.w};
#pragma unroll
            for (int g = 0; g < HID; g++) h1v[g] = fmaf(a, wr[g], h1v[g]);
        }
        float mu = b2[k];
#pragma unroll
        for (int h = 0; h < HID; h++) mu = fmaf(lrelu(h1v[h]), W2[k * HID + h], mu);

        int b = bbase + i;
        out[1 + (size_t)b * D_TOT + k] = mu;

        float sk = ss[(warp * 2 + i) * D_TOT + k];
        float diff = (sk - mu) * istd;
        lpsum += fmaf(-0.5f * diff, diff, -logstd - HALF_LOG2PI);
    }

#pragma unroll
    for (int o = 16; o > 0; o >>= 1) lpsum += __shfl_down_sync(0xffffffffu, lpsum, o);
    if (lane == 0) atomicAdd(&g_accum, lpsum);

    // finalize: last block writes out[0] and resets counters for graph replay
    __syncthreads();
    if (tid == 0) {
        __threadfence();
        unsigned int n = atomicAdd(&g_done, 1u);
        if (n == NB_ALL - 1) {
            float total = atomicAdd(&g_accum, 0.0f);
            out[0] = total * (1.0f / (float)BATCH);
            g_accum = 0.0f;
            g_done = 0u;
            g_sync = 0u;
            __threadfence();
        }
    }
}

// ---------------------------------------------------------------------------
extern "C" void kernel_launch(void* const* d_in, const int* in_sizes, int n_in,
                              void* d_out, int out_size) {
    const float* x      = (const float*)d_in[0];
    const float* z      = (const float*)d_in[1];
    const float* u      = (const float*)d_in[2];
    const float* mp     = (const float*)d_in[3];
    const float* W0     = (const float*)d_in[4];
    const float* b0     = (const float*)d_in[5];
    const float* W1     = (const float*)d_in[6];
    const float* b1     = (const float*)d_in[7];
    const float* W2     = (const float*)d_in[8];
    const float* b2     = (const float*)d_in[9];
    const float* logvar = (const float*)d_in[10];
    float* out = (float*)d_out;

    const int DYN_SMEM = (16 * D_TOT + STAGES * 16 * 32) * 4;   // 36864 B
    static int attr_done = 0;
    if (!attr_done) {
        cudaFuncSetAttribute(fused_kernel,
                             cudaFuncAttributeMaxDynamicSharedMemorySize, DYN_SMEM);
        attr_done = 1;
    }

    dim3 grid(8, 64);   // 8 k-tiles of 32 (k=64..319), 64 b-tiles of 16
    fused_kernel<<<grid, 256, DYN_SMEM>>>(x, z, u, mp, W0, b0, W1, b1, W2, b2,
                                          logvar, out);
}

// round 8
// speedup vs baseline: 2.2334x; 2.2334x over previous
#include <cuda_runtime.h>
#include <math.h>
#include <stdint.h>

#define D_TOT 320
#define DZ    64
#define DX    256
#define DK    256
#define HID   16
#define BATCH 1024
#define NEG   0.01f
#define HALF_LOG2PI 0.91893853320467274f

#define USTAGES 8            // u pipeline depth (j's ahead, per-warp cp.async)
#define NBATCH  80           // 320 j / 4 per batch
#define WBUFS   3            // W0t/E ring buffers
#define WBATCH_BYTES 8704    // 4j * (4*512B W0t + 128B E)

// smem float offsets
#define SS_OFF   0                       // 32*320 = 10240 floats
#define UR_OFF   10240                   // 8 stages * 1024 floats = 8192
#define WR_OFF   18432                   // 3 * 8704B = 26112B = 6528 floats
#define MB_OFF   (18432 + 6528)          // 3 mbarriers (u64)
#define SMEM_FLOATS (MB_OFF + 8)
#define DYN_SMEM (SMEM_FLOATS * 4)

// scratch (device globals — no allocation allowed)
__device__ __align__(16) float g_E[D_TOT * D_TOT];       // exp(-mask_param), [j][k]
__device__ ulonglong2 g_W0t[D_TOT * 4 * DK];             // [j][h4][k'], diag zeroed
__device__ float g_accum;
__device__ unsigned int g_done;

__device__ __forceinline__ float lrelu(float v) { return fmaxf(v, NEG * v); }

__device__ __forceinline__ unsigned long long pack2(float lo, float hi) {
    unsigned long long r;
    asm("mov.b64 %0, {%1, %2};" : "=l"(r) : "f"(lo), "f"(hi));
    return r;
}
__device__ __forceinline__ void unpack2(unsigned long long v, float& lo, float& hi) {
    asm("mov.b64 {%0, %1}, %2;" : "=f"(lo), "=f"(hi) : "l"(v));
}
__device__ __forceinline__ void ffma2(unsigned long long& d, unsigned long long a,
                                      unsigned long long b) {
    asm("fma.rn.f32x2 %0, %1, %2, %0;" : "+l"(d) : "l"(a), "l"(b));
}
__device__ __forceinline__ void cp_async16(uint32_t dst, const void* src) {
    asm volatile("cp.async.cg.shared.global [%0], [%1], 16;" :: "r"(dst), "l"(src));
}
__device__ __forceinline__ void mbar_init(uint32_t a, uint32_t cnt) {
    asm volatile("mbarrier.init.shared.b64 [%0], %1;" :: "r"(a), "r"(cnt) : "memory");
}
__device__ __forceinline__ void mbar_expect_tx(uint32_t a, uint32_t tx) {
    asm volatile("mbarrier.arrive.expect_tx.shared.b64 _, [%0], %1;"
                 :: "r"(a), "r"(tx) : "memory");
}
__device__ __forceinline__ void mbar_wait(uint32_t a, uint32_t ph) {
    uint32_t done;
    do {
        asm volatile("{\n\t.reg .pred p;\n\t"
                     "mbarrier.try_wait.parity.shared.b64 p, [%1], %2;\n\t"
                     "selp.b32 %0, 1, 0, p;\n\t}"
                     : "=r"(done) : "r"(a), "r"(ph) : "memory");
    } while (!done);
}
__device__ __forceinline__ void bulk_cp(uint32_t dst, const void* src,
                                        uint32_t bytes, uint32_t mbar) {
    asm volatile("cp.async.bulk.shared::cta.global.mbarrier::complete_tx::bytes "
                 "[%0], [%1], %2, [%3];"
                 :: "r"(dst), "l"(src), "r"(bytes), "r"(mbar) : "memory");
}

// ---------------------------------------------------------------------------
// Init: E = exp(-mask_param); W0 transpose with diag zeroed; std; counters.
// ---------------------------------------------------------------------------
__global__ void init_kernel(const float* __restrict__ mp,
                            const float* __restrict__ W0,
                            const float* __restrict__ logvar,
                            float* __restrict__ out) {
    int i = blockIdx.x * blockDim.x + threadIdx.x;
    if (i < D_TOT * 4 * DK) {
        int kp = i & (DK - 1);
        int h4 = (i >> 8) & 3;
        int j  = i >> 10;
        int k  = DZ + kp;
        float4 v;
        if (j == k) v = make_float4(0.f, 0.f, 0.f, 0.f);
        else        v = *(const float4*)(W0 + ((size_t)k * D_TOT + j) * HID + h4 * 4);
        ulonglong2 p;
        p.x = pack2(v.x, v.y);
        p.y = pack2(v.z, v.w);
        g_W0t[i] = p;
    }
    if (i < D_TOT * D_TOT) g_E[i] = expf(-mp[i]);
    if (i < D_TOT) out[1 + BATCH * D_TOT + i] = expf(0.5f * logvar[i]);
    if (i == 0) { g_accum = 0.0f; g_done = 0u; }
}

// ---------------------------------------------------------------------------
// Latent path: k < 64, only j == k contributes
// ---------------------------------------------------------------------------
__global__ void latent_kernel(const float* __restrict__ z,
                              const float* __restrict__ u,
                              const float* __restrict__ W0,
                              const float* __restrict__ b0,
                              const float* __restrict__ W1,
                              const float* __restrict__ b1,
                              const float* __restrict__ W2,
                              const float* __restrict__ b2,
                              const float* __restrict__ logvar,
                              float* __restrict__ out) {
    int tid = blockIdx.x * blockDim.x + threadIdx.x;
    int k = tid & (DZ - 1);
    int b = tid >> 6;

    float uu = u[((size_t)b * D_TOT + k) * D_TOT + k];
    float E  = g_E[k * D_TOT + k];
    float s  = z[b * DZ + k];
    float m = __fdividef(uu * s, fmaf(1.0f - uu, E, uu));

    float h1v[HID];
#pragma unroll
    for (int g = 0; g < HID; g++) h1v[g] = b1[k * HID + g];
#pragma unroll
    for (int h = 0; h < HID; h++) {
        float a = lrelu(fmaf(m, W0[((size_t)k * D_TOT + k) * HID + h], b0[k * HID + h]));
        const float* w1r = W1 + (k * HID + h) * HID;
#pragma unroll
        for (int g = 0; g < HID; g++) h1v[g] = fmaf(a, w1r[g], h1v[g]);
    }
    float mu = b2[k];
#pragma unroll
    for (int h = 0; h < HID; h++) mu = fmaf(lrelu(h1v[h]), W2[k * HID + h], mu);

    out[1 + (size_t)b * D_TOT + k] = mu;

    float logstd = 0.5f * logvar[k];
    float istd = __expf(-logstd);
    float diff = (s - mu) * istd;
    float lp = fmaf(-0.5f * diff, diff, -logstd - HALF_LOG2PI);
#pragma unroll
    for (int o = 16; o > 0; o >>= 1) lp += __shfl_down_sync(0xffffffffu, lp, o);
    if ((threadIdx.x & 31) == 0) atomicAdd(&g_accum, lp);
}

// ---------------------------------------------------------------------------
// Dense: k in [64,320). Block 256 thr: 32 k-lanes x 8 warps x 4 b/thread.
// W0t+E via block-shared cp.async.bulk + mbarrier ring (4-j batches, 3 bufs).
// u via per-warp cp.async group pipeline. Inner loop: LDS only.
// ---------------------------------------------------------------------------
__global__ void __launch_bounds__(256, 2)
dense_kernel(const float* __restrict__ x,
             const float* __restrict__ z,
             const float* __restrict__ u,
             const float* __restrict__ b0,
             const float* __restrict__ W1,
             const float* __restrict__ b1,
             const float* __restrict__ W2,
             const float* __restrict__ b2,
             const float* __restrict__ logvar,
             float* __restrict__ out) {
    extern __shared__ float dynsm[];
    float* ss = dynsm + SS_OFF;
    float* us = dynsm + UR_OFF;
    char*  wr = (char*)(dynsm + WR_OFF);

    int tid  = threadIdx.x;
    int lane = tid & 31;
    int warp = tid >> 5;
    int kx   = blockIdx.x;                      // k-tile
    int k    = DZ + kx * 32 + lane;
    int bbase = blockIdx.y * 32 + warp * 4;

    uint32_t smem_base = (uint32_t)__cvta_generic_to_shared(dynsm);
    uint32_t mb_base   = smem_base + MB_OFF * 4;
    uint32_t wr_base   = smem_base + WR_OFF * 4;

    if (tid == 0) {
#pragma unroll
        for (int i = 0; i < WBUFS; i++) mbar_init(mb_base + i * 8, 1);
    }

    // stage all_var
    for (int idx = tid; idx < 32 * D_TOT; idx += 256) {
        int bl = idx / D_TOT;
        int j  = idx - bl * D_TOT;
        int b  = blockIdx.y * 32 + bl;
        ss[idx] = (j < DZ) ? z[b * DZ + j] : x[b * DX + (j - DZ)];
    }
    __syncthreads();      // mbarriers visible + ss ready

    // --- W0t/E batch issue helper (tid 0 only) ---
    auto issue_batch = [&](int m) {
        int buf = m % WBUFS;
        uint32_t mb = mb_base + buf * 8;
        uint32_t base = wr_base + buf * WBATCH_BYTES;
        mbar_expect_tx(mb, WBATCH_BYTES);
        int j0 = m * 4;
#pragma unroll
        for (int jj = 0; jj < 4; jj++) {
#pragma unroll
            for (int r = 0; r < 4; r++)
                bulk_cp(base + jj * 2048 + r * 512,
                        g_W0t + ((size_t)((j0 + jj) * 4 + r) * DK + kx * 32),
                        512, mb);
            bulk_cp(base + 8192 + jj * 128,
                    g_E + (size_t)(j0 + jj) * D_TOT + DZ + kx * 32,
                    128, mb);
        }
    };

    if (tid == 0) { issue_batch(0); issue_batch(1); }

    // --- u pipeline prologue (per-warp, as R5) ---
    int lb = lane >> 3;
    int lc = lane & 7;
    const float* usrc = u + ((size_t)(bbase + lb) * D_TOT) * D_TOT
                          + (DZ + kx * 32) + lc * 4;
    uint32_t us_base = smem_base + UR_OFF * 4;
    uint32_t wadr = us_base + (((warp * 4 + lb) * 32 + lc * 4) << 2);
    const float* ur0 = us + warp * 4 * 32 + lane;

#pragma unroll
    for (int s = 0; s < USTAGES - 1; s++) {
        cp_async16(wadr + (s << 12), usrc + (size_t)s * D_TOT);
        asm volatile("cp.async.commit_group;");
    }

    unsigned long long acc[4][8];
#pragma unroll
    for (int h2 = 0; h2 < 8; h2++) {
        unsigned long long p = pack2(b0[k * HID + 2 * h2], b0[k * HID + 2 * h2 + 1]);
#pragma unroll
        for (int i = 0; i < 4; i++) acc[i][h2] = p;
    }
    const float* srow = &ss[(warp * 4) * D_TOT];

    // --- main loop: 80 batches of 4 j ---
    for (int m = 0; m < NBATCH; m++) {
        if (tid == 0 && m + 2 < NBATCH) issue_batch(m + 2);

        int buf = m % WBUFS;
        mbar_wait(mb_base + buf * 8, (unsigned)(m / WBUFS) & 1u);

        const ulonglong2* wb = (const ulonglong2*)(wr + buf * WBATCH_BYTES);
        const float* eb = (const float*)(wr + buf * WBATCH_BYTES + 8192);

#pragma unroll
        for (int jj = 0; jj < 4; jj++) {
            int j = m * 4 + jj;
            asm volatile("cp.async.wait_group %0;" :: "n"(USTAGES - 2));
            __syncwarp();

            float E = eb[jj * 32 + lane];
            ulonglong2 w01 = wb[jj * 128 + 0 * 32 + lane];
            ulonglong2 w23 = wb[jj * 128 + 1 * 32 + lane];
            ulonglong2 w45 = wb[jj * 128 + 2 * 32 + lane];
            ulonglong2 w67 = wb[jj * 128 + 3 * 32 + lane];

            const float* ur = ur0 + ((j & (USTAGES - 1)) << 10);
            float u0 = ur[0];
            float u1 = ur[32];
            float u2 = ur[64];
            float u3 = ur[96];

            {
                float sj = srow[j];
                float mm0 = __fdividef(u0 * sj, fmaf(1.0f - u0, E, u0));
                unsigned long long mm = pack2(mm0, mm0);
                ffma2(acc[0][0], mm, w01.x); ffma2(acc[0][1], mm, w01.y);
                ffma2(acc[0][2], mm, w23.x); ffma2(acc[0][3], mm, w23.y);
                ffma2(acc[0][4], mm, w45.x); ffma2(acc[0][5], mm, w45.y);
                ffma2(acc[0][6], mm, w67.x); ffma2(acc[0][7], mm, w67.y);
            }
            {
                float sj = srow[D_TOT + j];
                float mm0 = __fdividef(u1 * sj, fmaf(1.0f - u1, E, u1));
                unsigned long long mm = pack2(mm0, mm0);
                ffma2(acc[1][0], mm, w01.x); ffma2(acc[1][1], mm, w01.y);
                ffma2(acc[1][2], mm, w23.x); ffma2(acc[1][3], mm, w23.y);
                ffma2(acc[1][4], mm, w45.x); ffma2(acc[1][5], mm, w45.y);
                ffma2(acc[1][6], mm, w67.x); ffma2(acc[1][7], mm, w67.y);
            }
            {
                float sj = srow[2 * D_TOT + j];
                float mm0 = __fdividef(u2 * sj, fmaf(1.0f - u2, E, u2));
                unsigned long long mm = pack2(mm0, mm0);
                ffma2(acc[2][0], mm, w01.x); ffma2(acc[2][1], mm, w01.y);
                ffma2(acc[2][2], mm, w23.x); ffma2(acc[2][3], mm, w23.y);
                ffma2(acc[2][4], mm, w45.x); ffma2(acc[2][5], mm, w45.y);
                ffma2(acc[2][6], mm, w67.x); ffma2(acc[2][7], mm, w67.y);
            }
            {
                float sj = srow[3 * D_TOT + j];
                float mm0 = __fdividef(u3 * sj, fmaf(1.0f - u3, E, u3));
                unsigned long long mm = pack2(mm0, mm0);
                ffma2(acc[3][0], mm, w01.x); ffma2(acc[3][1], mm, w01.y);
                ffma2(acc[3][2], mm, w23.x); ffma2(acc[3][3], mm, w23.y);
                ffma2(acc[3][4], mm, w45.x); ffma2(acc[3][5], mm, w45.y);
                ffma2(acc[3][6], mm, w67.x); ffma2(acc[3][7], mm, w67.y);
            }

            int jn = j + USTAGES - 1;
            if (jn < D_TOT)
                cp_async16(wadr + ((jn & (USTAGES - 1)) << 12), usrc + (size_t)jn * D_TOT);
            asm volatile("cp.async.commit_group;");
        }
        __syncthreads();     // buffer recycle fence
    }

    // epilogue
    float logstd = 0.5f * logvar[k];
    float istd = __expf(-logstd);
    float lpsum = 0.0f;

#pragma unroll
    for (int i = 0; i < 4; i++) {
        float a0[HID];
#pragma unroll
        for (int h2 = 0; h2 < 8; h2++) unpack2(acc[i][h2], a0[2 * h2], a0[2 * h2 + 1]);

        float h1v[HID];
#pragma unroll
        for (int g = 0; g < HID; g++) h1v[g] = b1[k * HID + g];
#pragma unroll
        for (int h = 0; h < HID; h++) {
            float a = lrelu(a0[h]);
            const float4* w1p = (const float4*)(W1 + ((size_t)k * HID + h) * HID);
            float4 r0 = w1p[0], r1 = w1p[1], r2 = w1p[2], r3 = w1p[3];
            float wrg[HID] = {r0.x, r0.y, r0.z, r0.w, r1.x, r1.y, r1.z, r1.w,
                              r2.x, r2.y, r2.z, r2.w, r3.x, r3.y, r3.z, r3.w};
#pragma unroll
            for (int g = 0; g < HID; g++) h1v[g] = fmaf(a, wrg[g], h1v[g]);
        }
        float mu = b2[k];
#pragma unroll
        for (int h = 0; h < HID; h++) mu = fmaf(lrelu(h1v[h]), W2[k * HID + h], mu);

        int b = bbase + i;
        out[1 + (size_t)b * D_TOT + k] = mu;

        float sk = ss[(warp * 4 + i) * D_TOT + k];
        float diff = (sk - mu) * istd;
        lpsum += fmaf(-0.5f * diff, diff, -logstd - HALF_LOG2PI);
    }

#pragma unroll
    for (int o = 16; o > 0; o >>= 1) lpsum += __shfl_down_sync(0xffffffffu, lpsum, o);
    if (lane == 0) atomicAdd(&g_accum, lpsum);

    // fused finalize
    __syncthreads();
    if (tid == 0) {
        __threadfence();
        unsigned int n = atomicAdd(&g_done, 1u);
        if (n == gridDim.x * gridDim.y - 1) {
            float total = atomicAdd(&g_accum, 0.0f);
            out[0] = total * (1.0f / (float)BATCH);
        }
    }
}

// ---------------------------------------------------------------------------
extern "C" void kernel_launch(void* const* d_in, const int* in_sizes, int n_in,
                              void* d_out, int out_size) {
    const float* x      = (const float*)d_in[0];
    const float* z      = (const float*)d_in[1];
    const float* u      = (const float*)d_in[2];
    const float* mp     = (const float*)d_in[3];
    const float* W0     = (const float*)d_in[4];
    const float* b0     = (const float*)d_in[5];
    const float* W1     = (const float*)d_in[6];
    const float* b1     = (const float*)d_in[7];
    const float* W2     = (const float*)d_in[8];
    const float* b2     = (const float*)d_in[9];
    const float* logvar = (const float*)d_in[10];
    float* out = (float*)d_out;

    static int attr_done = 0;
    if (!attr_done) {
        cudaFuncSetAttribute(dense_kernel,
                             cudaFuncAttributeMaxDynamicSharedMemorySize, DYN_SMEM);
        attr_done = 1;
    }

    {
        int total = D_TOT * 4 * DK;
        init_kernel<<<(total + 255) / 256, 256>>>(mp, W0, logvar, out);
    }
    latent_kernel<<<(BATCH * DZ) / 256, 256>>>(z, u, W0, b0, W1, b1, W2, b2, logvar, out);
    {
        dim3 grid(8, 32);   // 256 blocks — single wave at occupancy 2
        dense_kernel<<<grid, 256, DYN_SMEM>>>(x, z, u, b0, W1, b1, W2, b2, logvar, out);
    }
}